// round 3
// baseline (speedup 1.0000x reference)
#include <cuda_runtime.h>
#include <math.h>

#define IMG    224
#define PSIDE  112
#define P      12544
#define BATCH  32
#define NC     10
#define KP     2                 // patches per thread (consecutive in a row)
#define GB     2                 // batches per thread
#define ROWG   (PSIDE / KP)      // 56 patch-groups per row
#define PG     (P / KP)          // 6272 patch-groups
#define TPB    224               // 7 warps
#define BLKX   (PG / TPB)        // 28
#define NBG    (BATCH / GB)      // 16
#define NBLOCKS (BLKX * NBG)     // 448
#define NWARP  (TPB / 32)

__device__ float    g_part[BATCH * BLKX * NC];
__device__ unsigned g_ctr = 0;

__device__ __forceinline__ float ldcg(const float* p) {
    float v; asm volatile("ld.global.cg.f32 %0, [%1];" : "=f"(v) : "l"(p)); return v;
}

// Closed-form 4-qubit block (circuit factorizes into pairs {0,1},{2,3};
// final RZ is a pure phase):
//   Z0 = cos(d0+p0)
//   Z1 = cos(d0+p0) * cos(p1) * cos(d1)
//   Z2 = cos(p4)cos(d2) + sin(p2)sin(p4) * sin(d2) * sin(d3+p3)
//   Z3 = cos(d2) * cos(d3+p3)
// consts c[7] = {cos p0, sin p0, cos p1, cos p3, sin p3, cos p4, sin p2*sin p4}
__device__ __forceinline__ void qblock(const float* __restrict__ c,
                                       float d0, float d1, float d2, float d3,
                                       float& z0, float& z1, float& z2, float& z3) {
    float s0, c0; __sincosf(d0, &s0, &c0);
    float cA = c0 * c[0] - s0 * c[1];
    z0 = cA;
    z1 = cA * c[2] * __cosf(d1);
    float s2, c2; __sincosf(d2, &s2, &c2);
    float s3, c3; __sincosf(d3, &s3, &c3);
    float cB = c3 * c[3] - s3 * c[4];
    float sB = s3 * c[3] + c3 * c[4];
    z2 = c[5] * c2 + c[6] * s2 * sB;
    z3 = c2 * cB;
}

__global__ void __launch_bounds__(TPB, 3)
k_fused(const float* __restrict__ x,
        const float* __restrict__ rl1, const float* __restrict__ rl2,
        const float* __restrict__ W,   const float* __restrict__ bias,
        float* __restrict__ out) {
    const int tid  = threadIdx.x;
    const int pg   = blockIdx.x * TPB + tid;       // patch-group [0, 6272)
    const int b0   = blockIdx.y * GB;              // first batch of this group
    const int r    = pg / ROWG;                    // patch row [0, 112)
    const int g    = pg - r * ROWG;                // group in row [0, 56)
    const bool edge = (g == ROWG - 1);             // second patch at col 222

    // ---- per-block circuit constants in shared (threads 0,1 compute) ----
    __shared__ float s_c[14];
    if (tid < 2) {
        const float* prm = (tid == 0) ? rl1 : rl2;
        float* c = s_c + tid * 7;
        float s, co;
        __sincosf(__ldg(prm + 0), &s, &co); c[0] = co; c[1] = s;
        c[2] = __cosf(__ldg(prm + 1));
        __sincosf(__ldg(prm + 3), &s, &co); c[3] = co; c[4] = s;
        float s4, c4; __sincosf(__ldg(prm + 4), &s4, &c4);
        c[5] = c4;
        c[6] = __sinf(__ldg(prm + 2)) * s4;
    }
    __syncthreads();

    // ---- x loads: row0[4g..4g+4], row1[4g..4g+3] per batch ----
    const float* Xb = x + (size_t)b0 * (IMG * IMG) + (2 * r) * IMG + g * (2 * KP);
    float4 r0[GB], r1[GB]; float f4[GB];
    #pragma unroll
    for (int q = 0; q < GB; q++) {
        const float* p0 = Xb + q * (IMG * IMG);
        r0[q] = *(const float4*)p0;
        r1[q] = *(const float4*)(p0 + IMG);
        f4[q] = edge ? 0.f : __ldg(p0 + 4);
    }

    float acc[GB][NC];
    #pragma unroll
    for (int q = 0; q < GB; q++)
        #pragma unroll
        for (int c = 0; c < NC; c++) acc[q][c] = 0.f;

    const float4* __restrict__ W4 = (const float4*)W;
    const int pbase = r * PSIDE + g * KP;

    #pragma unroll
    for (int i = 0; i < KP; i++) {
        float z0[GB], z1[GB], z2[GB], z3[GB];
        #pragma unroll
        for (int q = 0; q < GB; q++) {
            float f0, f1, f2, f3;
            if (i == 0) { f0 = r0[q].x; f1 = r0[q].y; f2 = r0[q].z; f3 = r1[q].x; }
            else {
                f0 = r0[q].z; f1 = r0[q].w;
                if (edge) { f2 = r1[q].z; f3 = r1[q].w; }
                else      { f2 = f4[q];   f3 = r1[q].z; }
            }
            float m0, m1, m2, m3, n0, n1, n2, n3;
            qblock(s_c,     f0, f1, f2, f3, m0, m1, m2, m3);
            qblock(s_c + 7, m0, m1, m2, m3, n0, n1, n2, n3);
            z0[q] = m0 + n0; z1[q] = m1 + n1; z2[q] = m2 + n2; z3[q] = m3 + n3;
        }
        const float4* wp = W4 + pbase + i;
        #pragma unroll
        for (int c = 0; c < NC; c++) {
            float4 w = __ldg(wp + c * P);
            #pragma unroll
            for (int q = 0; q < GB; q++)
                acc[q][c] = fmaf(z0[q], w.x, fmaf(z1[q], w.y,
                             fmaf(z2[q], w.z, fmaf(z3[q], w.w, acc[q][c]))));
        }
    }

    // ---- warp reduce, then cross-warp via shared ----
    #pragma unroll
    for (int q = 0; q < GB; q++)
        #pragma unroll
        for (int c = 0; c < NC; c++) {
            float v = acc[q][c];
            #pragma unroll
            for (int off = 16; off > 0; off >>= 1)
                v += __shfl_down_sync(0xffffffffu, v, off);
            acc[q][c] = v;
        }

    __shared__ float sm[NWARP][GB * NC];
    const int warp = tid >> 5, lane = tid & 31;
    if (lane == 0) {
        #pragma unroll
        for (int q = 0; q < GB; q++)
            #pragma unroll
            for (int c = 0; c < NC; c++) sm[warp][q * NC + c] = acc[q][c];
    }
    __syncthreads();

    if (tid < GB * NC) {
        const int q = tid / NC, c = tid - q * NC;
        float s = 0.f;
        #pragma unroll
        for (int w = 0; w < NWARP; w++) s += sm[w][tid];
        g_part[((b0 + q) * BLKX + blockIdx.x) * NC + c] = s;
    }

    // ---- grid-wide finalize by the last block to finish ----
    __shared__ int lastFlag;
    __threadfence();
    __syncthreads();
    if (tid == 0) lastFlag = (atomicAdd(&g_ctr, 1u) == NBLOCKS - 1);
    __syncthreads();
    if (!lastFlag) return;

    __threadfence();   // acquire: all partials visible
    if (tid < BATCH) {
        float lg[NC];
        #pragma unroll
        for (int c = 0; c < NC; c++) {
            float s = __ldg(bias + c);
            const float* pp = g_part + (tid * BLKX) * NC + c;
            #pragma unroll
            for (int t = 0; t < BLKX; t++) s += ldcg(pp + t * NC);
            lg[c] = s;
        }
        float mx = lg[0];
        #pragma unroll
        for (int c = 1; c < NC; c++) mx = fmaxf(mx, lg[c]);
        float se = 0.f;
        #pragma unroll
        for (int c = 0; c < NC; c++) se += expf(lg[c] - mx);
        const float lse = logf(se);
        #pragma unroll
        for (int c = 0; c < NC; c++) out[tid * NC + c] = lg[c] - mx - lse;
    }
    if (tid == 0) g_ctr = 0;   // reset for next graph replay
}

extern "C" void kernel_launch(void* const* d_in, const int* in_sizes, int n_in,
                              void* d_out, int out_size) {
    const float* x    = (const float*)d_in[0];
    const float* rl1  = (const float*)d_in[1];
    const float* rl2  = (const float*)d_in[2];
    const float* W    = (const float*)d_in[3];
    const float* bias = (const float*)d_in[4];
    float* out        = (float*)d_out;

    k_fused<<<dim3(BLKX, NBG), TPB>>>(x, rl1, rl2, W, bias, out);
}